// round 1
// baseline (speedup 1.0000x reference)
#include <cuda_runtime.h>
#include <cstdint>

#define NN       512
#define NB       16
#define KTOP     50
#define NITERS   100
#define CL       8      // CTAs per cluster (one cluster per batch)
#define RPC      64     // rows/cols owned per CTA
#define NTHREADS 512

__device__ __forceinline__ uint32_t smem_u32(const void* p) {
    return (uint32_t)__cvta_generic_to_shared(p);
}
__device__ __forceinline__ float ex2f_(float x) {
    float r; asm("ex2.approx.ftz.f32 %0, %1;" : "=f"(r) : "f"(x)); return r;
}
__device__ __forceinline__ float lg2f_(float x) {
    float r; asm("lg2.approx.f32 %0, %1;" : "=f"(r) : "f"(x)); return r;
}
__device__ __forceinline__ void cluster_sync_() {
    asm volatile("barrier.cluster.arrive.aligned;" ::: "memory");
    asm volatile("barrier.cluster.wait.aligned;" ::: "memory");
}
__device__ __forceinline__ uint32_t ctarank_() {
    uint32_t r; asm("mov.u32 %0, %%cluster_ctarank;" : "=r"(r)); return r;
}
// Store val to the same smem offset in cluster CTA `rank` (includes self).
__device__ __forceinline__ void st_cluster_f32(uint32_t laddr, uint32_t rank, float v) {
    asm volatile(
        "{\n\t.reg .b32 ra;\n\t"
        "mapa.shared::cluster.u32 ra, %0, %1;\n\t"
        "st.shared::cluster.f32 [ra], %2;\n\t}"
        :: "r"(laddr), "r"(rank), "f"(v) : "memory");
}

// log_P = L + U[i] + V[j],  L[i,j] = nk2*(s_i - t_j)^2  (log2 domain)
// half-step 1: V_j = -lse2_i(L_ij + U_i)
// half-step 2: U_i = -lse2_j(L_ij + V_j)
__global__ void __launch_bounds__(NTHREADS, 1) __cluster_dims__(CL, 1, 1)
sinkhorn_topk_kernel(const float* __restrict__ scores, float* __restrict__ out)
{
    __shared__ float s_sh[NN];   // scores (original order)
    __shared__ float t_sh[NN];   // scores sorted descending
    __shared__ float U_sh[NN];   // row potentials (log2 units)
    __shared__ float V_sh[NN];   // col potentials (log2 units)

    const int tid   = threadIdx.x;
    const int lane  = tid & 31;
    const int warp  = tid >> 5;
    const int rank  = (int)ctarank_();
    const int batch = blockIdx.x / CL;
    const float* sg = scores + batch * NN;

    float sv = sg[tid];
    s_sh[tid] = sv;
    t_sh[tid] = sv;
    U_sh[tid] = 0.0f;
    V_sh[tid] = 0.0f;
    __syncthreads();

    // Bitonic sort t_sh descending (once; 512 elems, 512 threads)
    for (int k = 2; k <= NN; k <<= 1) {
        for (int j = k >> 1; j > 0; j >>= 1) {
            int ixj = tid ^ j;
            if (ixj > tid) {
                float a = t_sh[tid];
                float b = t_sh[ixj];
                bool desc = ((tid & k) == 0);
                if (desc ? (a < b) : (a > b)) { t_sh[tid] = b; t_sh[ixj] = a; }
            }
            __syncthreads();
        }
    }

    // lane-resident operands: lane handles indices {lane + 32*q}
    float s_r[16], t_r[16];
#pragma unroll
    for (int q = 0; q < 16; q++) {
        s_r[q] = s_sh[lane + 32 * q];
        t_r[q] = t_sh[lane + 32 * q];
    }

    const float nk2 = -1442.6950408889634f;   // -log2(e)/EPSILON
    const uint32_t Ub = smem_u32(U_sh);
    const uint32_t Vb = smem_u32(V_sh);
    const int base = rank * RPC + warp * 4;   // 4 rows/cols per warp

    for (int it = 0; it < NITERS; it++) {
        // ---- half-step 1: columns (reduce over i) ----
        float Ur[16];
#pragma unroll
        for (int q = 0; q < 16; q++) Ur[q] = U_sh[lane + 32 * q];
#pragma unroll 1
        for (int c = 0; c < 4; c++) {
            const int j = base + c;
            const float tj = t_sh[j];
            float x[16];
            float m = -3.402823466e38f;
#pragma unroll
            for (int q = 0; q < 16; q++) {
                float d = s_r[q] - tj;
                x[q] = fmaf(d * nk2, d, Ur[q]);
                m = fmaxf(m, x[q]);
            }
#pragma unroll
            for (int o = 16; o > 0; o >>= 1)
                m = fmaxf(m, __shfl_xor_sync(0xffffffffu, m, o));
            float sum = 0.0f;
#pragma unroll
            for (int q = 0; q < 16; q++) sum += ex2f_(x[q] - m);
#pragma unroll
            for (int o = 16; o > 0; o >>= 1)
                sum += __shfl_xor_sync(0xffffffffu, sum, o);
            const float vj = -(m + lg2f_(sum));       // all lanes hold it
            if (lane < CL) st_cluster_f32(Vb + (uint32_t)j * 4u, (uint32_t)lane, vj);
        }
        cluster_sync_();

        // ---- half-step 2: rows (reduce over j) ----
        float Vr[16];
#pragma unroll
        for (int q = 0; q < 16; q++) Vr[q] = V_sh[lane + 32 * q];
#pragma unroll 1
        for (int c = 0; c < 4; c++) {
            const int i = base + c;
            const float si = s_sh[i];
            float x[16];
            float m = -3.402823466e38f;
#pragma unroll
            for (int q = 0; q < 16; q++) {
                float d = si - t_r[q];
                x[q] = fmaf(d * nk2, d, Vr[q]);
                m = fmaxf(m, x[q]);
            }
#pragma unroll
            for (int o = 16; o > 0; o >>= 1)
                m = fmaxf(m, __shfl_xor_sync(0xffffffffu, m, o));
            float sum = 0.0f;
#pragma unroll
            for (int q = 0; q < 16; q++) sum += ex2f_(x[q] - m);
#pragma unroll
            for (int o = 16; o > 0; o >>= 1)
                sum += __shfl_xor_sync(0xffffffffu, sum, o);
            const float ui = -(m + lg2f_(sum));
            if (lane < CL) st_cluster_f32(Ub + (uint32_t)i * 4u, (uint32_t)lane, ui);
        }
        cluster_sync_();
    }

    // ---- output: out[i] = sum_{j<K} 2^(L_ij + U_i + V_j) ----
#pragma unroll 1
    for (int c = 0; c < 4; c++) {
        const int i = base + c;
        const float si = s_sh[i];
        const float ui = U_sh[i];
        float acc = 0.0f;
        for (int jj = lane; jj < KTOP; jj += 32) {
            float d = si - t_sh[jj];
            acc += ex2f_(fmaf(d * nk2, d, ui + V_sh[jj]));
        }
#pragma unroll
        for (int o = 16; o > 0; o >>= 1)
            acc += __shfl_xor_sync(0xffffffffu, acc, o);
        if (lane == 0) out[batch * NN + i] = acc;
    }
}

extern "C" void kernel_launch(void* const* d_in, const int* in_sizes, int n_in,
                              void* d_out, int out_size) {
    const float* scores = (const float*)d_in[0];
    float* outp = (float*)d_out;
    sinkhorn_topk_kernel<<<NB * CL, NTHREADS>>>(scores, outp);
}

// round 2
// speedup vs baseline: 1.0069x; 1.0069x over previous
#include <cuda_runtime.h>
#include <cstdint>

#define NN       512
#define NB       16
#define KTOP     50
#define NITERS   100
#define CL       8      // CTAs per cluster (one cluster per batch)
#define RPC      64     // rows/cols owned per CTA
#define NTHREADS 512

__device__ __forceinline__ uint32_t smem_u32(const void* p) {
    return (uint32_t)__cvta_generic_to_shared(p);
}
__device__ __forceinline__ float ex2f_(float x) {
    float r; asm("ex2.approx.ftz.f32 %0, %1;" : "=f"(r) : "f"(x)); return r;
}
__device__ __forceinline__ float lg2f_(float x) {
    float r; asm("lg2.approx.f32 %0, %1;" : "=f"(r) : "f"(x)); return r;
}
__device__ __forceinline__ void cluster_sync_() {
    asm volatile("barrier.cluster.arrive.aligned;" ::: "memory");
    asm volatile("barrier.cluster.wait.aligned;" ::: "memory");
}
__device__ __forceinline__ uint32_t ctarank_() {
    uint32_t r; asm("mov.u32 %0, %%cluster_ctarank;" : "=r"(r)); return r;
}
// Store val to the same smem offset in cluster CTA `rank` (includes self).
__device__ __forceinline__ void st_cluster_f32(uint32_t laddr, uint32_t rank, float v) {
    asm volatile(
        "{\n\t.reg .b32 ra;\n\t"
        "mapa.shared::cluster.u32 ra, %0, %1;\n\t"
        "st.shared::cluster.f32 [ra], %2;\n\t}"
        :: "r"(laddr), "r"(rank), "f"(v) : "memory");
}

// log_P = L + U[i] + V[j],  L[i,j] = nk2*(s_i - t_j)^2  (log2 domain)
// half-step 1: V_j = -lse2_i(L_ij + U_i)
// half-step 2: U_i = -lse2_j(L_ij + V_j)
__global__ void __launch_bounds__(NTHREADS, 1) __cluster_dims__(CL, 1, 1)
sinkhorn_topk_kernel(const float* __restrict__ scores, float* __restrict__ out)
{
    __shared__ float s_sh[NN];   // scores (original order)
    __shared__ float t_sh[NN];   // scores sorted descending
    __shared__ float U_sh[NN];   // row potentials (log2 units)
    __shared__ float V_sh[NN];   // col potentials (log2 units)

    const int tid   = threadIdx.x;
    const int lane  = tid & 31;
    const int warp  = tid >> 5;
    const int rank  = (int)ctarank_();
    const int batch = blockIdx.x / CL;
    const float* sg = scores + batch * NN;

    float sv = sg[tid];
    s_sh[tid] = sv;
    t_sh[tid] = sv;
    U_sh[tid] = 0.0f;
    V_sh[tid] = 0.0f;
    __syncthreads();

    // Bitonic sort t_sh descending (once; 512 elems, 512 threads)
    for (int k = 2; k <= NN; k <<= 1) {
        for (int j = k >> 1; j > 0; j >>= 1) {
            int ixj = tid ^ j;
            if (ixj > tid) {
                float a = t_sh[tid];
                float b = t_sh[ixj];
                bool desc = ((tid & k) == 0);
                if (desc ? (a < b) : (a > b)) { t_sh[tid] = b; t_sh[ixj] = a; }
            }
            __syncthreads();
        }
    }

    // lane-resident operands: lane handles indices {lane + 32*q}
    float s_r[16], t_r[16];
#pragma unroll
    for (int q = 0; q < 16; q++) {
        s_r[q] = s_sh[lane + 32 * q];
        t_r[q] = t_sh[lane + 32 * q];
    }

    const float nk2 = -1442.6950408889634f;   // -log2(e)/EPSILON
    const uint32_t Ub = smem_u32(U_sh);
    const uint32_t Vb = smem_u32(V_sh);
    const int base = rank * RPC + warp * 4;   // 4 rows/cols per warp

    for (int it = 0; it < NITERS; it++) {
        // ---- half-step 1: columns (reduce over i) ----
        float Ur[16];
#pragma unroll
        for (int q = 0; q < 16; q++) Ur[q] = U_sh[lane + 32 * q];
#pragma unroll 1
        for (int c = 0; c < 4; c++) {
            const int j = base + c;
            const float tj = t_sh[j];
            float x[16];
            float m = -3.402823466e38f;
#pragma unroll
            for (int q = 0; q < 16; q++) {
                float d = s_r[q] - tj;
                x[q] = fmaf(d * nk2, d, Ur[q]);
                m = fmaxf(m, x[q]);
            }
#pragma unroll
            for (int o = 16; o > 0; o >>= 1)
                m = fmaxf(m, __shfl_xor_sync(0xffffffffu, m, o));
            float sum = 0.0f;
#pragma unroll
            for (int q = 0; q < 16; q++) sum += ex2f_(x[q] - m);
#pragma unroll
            for (int o = 16; o > 0; o >>= 1)
                sum += __shfl_xor_sync(0xffffffffu, sum, o);
            const float vj = -(m + lg2f_(sum));       // all lanes hold it
            if (lane < CL) st_cluster_f32(Vb + (uint32_t)j * 4u, (uint32_t)lane, vj);
        }
        cluster_sync_();

        // ---- half-step 2: rows (reduce over j) ----
        float Vr[16];
#pragma unroll
        for (int q = 0; q < 16; q++) Vr[q] = V_sh[lane + 32 * q];
#pragma unroll 1
        for (int c = 0; c < 4; c++) {
            const int i = base + c;
            const float si = s_sh[i];
            float x[16];
            float m = -3.402823466e38f;
#pragma unroll
            for (int q = 0; q < 16; q++) {
                float d = si - t_r[q];
                x[q] = fmaf(d * nk2, d, Vr[q]);
                m = fmaxf(m, x[q]);
            }
#pragma unroll
            for (int o = 16; o > 0; o >>= 1)
                m = fmaxf(m, __shfl_xor_sync(0xffffffffu, m, o));
            float sum = 0.0f;
#pragma unroll
            for (int q = 0; q < 16; q++) sum += ex2f_(x[q] - m);
#pragma unroll
            for (int o = 16; o > 0; o >>= 1)
                sum += __shfl_xor_sync(0xffffffffu, sum, o);
            const float ui = -(m + lg2f_(sum));
            if (lane < CL) st_cluster_f32(Ub + (uint32_t)i * 4u, (uint32_t)lane, ui);
        }
        cluster_sync_();
    }

    // ---- output: out[i] = sum_{j<K} 2^(L_ij + U_i + V_j) ----
#pragma unroll 1
    for (int c = 0; c < 4; c++) {
        const int i = base + c;
        const float si = s_sh[i];
        const float ui = U_sh[i];
        float acc = 0.0f;
        for (int jj = lane; jj < KTOP; jj += 32) {
            float d = si - t_sh[jj];
            acc += ex2f_(fmaf(d * nk2, d, ui + V_sh[jj]));
        }
#pragma unroll
        for (int o = 16; o > 0; o >>= 1)
            acc += __shfl_xor_sync(0xffffffffu, acc, o);
        if (lane == 0) out[batch * NN + i] = acc;
    }
}

extern "C" void kernel_launch(void* const* d_in, const int* in_sizes, int n_in,
                              void* d_out, int out_size) {
    const float* scores = (const float*)d_in[0];
    float* outp = (float*)d_out;
    sinkhorn_topk_kernel<<<NB * CL, NTHREADS>>>(scores, outp);
}

// round 3
// speedup vs baseline: 1.0084x; 1.0016x over previous
#include <cuda_runtime.h>
#include <cstdint>

#define NN       512
#define NB       16
#define KTOP     50
#define NITERS   100
#define CL       8      // CTAs per cluster (one cluster per batch)
#define RPC      64     // rows/cols owned per CTA
#define NTHREADS 512

__device__ __forceinline__ uint32_t smem_u32(const void* p) {
    return (uint32_t)__cvta_generic_to_shared(p);
}
__device__ __forceinline__ float ex2f_(float x) {
    float r; asm("ex2.approx.ftz.f32 %0, %1;" : "=f"(r) : "f"(x)); return r;
}
__device__ __forceinline__ float lg2f_(float x) {
    float r; asm("lg2.approx.f32 %0, %1;" : "=f"(r) : "f"(x)); return r;
}
__device__ __forceinline__ void cluster_sync_() {
    asm volatile("barrier.cluster.arrive.aligned;" ::: "memory");
    asm volatile("barrier.cluster.wait.aligned;" ::: "memory");
}
__device__ __forceinline__ uint32_t ctarank_() {
    uint32_t r; asm("mov.u32 %0, %%cluster_ctarank;" : "=r"(r)); return r;
}
// Store val to the same smem offset in cluster CTA `rank` (includes self).
__device__ __forceinline__ void st_cluster_f32(uint32_t laddr, uint32_t rank, float v) {
    asm volatile(
        "{\n\t.reg .b32 ra;\n\t"
        "mapa.shared::cluster.u32 ra, %0, %1;\n\t"
        "st.shared::cluster.f32 [ra], %2;\n\t}"
        :: "r"(laddr), "r"(rank), "f"(v) : "memory");
}

// log_P = L + U[i] + V[j],  L[i,j] = nk2*(s_i - t_j)^2  (log2 domain)
// half-step 1: V_j = -lse2_i(L_ij + U_i)
// half-step 2: U_i = -lse2_j(L_ij + V_j)
__global__ void __launch_bounds__(NTHREADS, 1) __cluster_dims__(CL, 1, 1)
sinkhorn_topk_kernel(const float* __restrict__ scores, float* __restrict__ out)
{
    __shared__ float s_sh[NN];   // scores (original order)
    __shared__ float t_sh[NN];   // scores sorted descending
    __shared__ float U_sh[NN];   // row potentials (log2 units)
    __shared__ float V_sh[NN];   // col potentials (log2 units)

    const int tid   = threadIdx.x;
    const int lane  = tid & 31;
    const int warp  = tid >> 5;
    const int rank  = (int)ctarank_();
    const int batch = blockIdx.x / CL;
    const float* sg = scores + batch * NN;

    float sv = sg[tid];
    s_sh[tid] = sv;
    t_sh[tid] = sv;
    U_sh[tid] = 0.0f;
    V_sh[tid] = 0.0f;
    __syncthreads();

    // Bitonic sort t_sh descending (once; 512 elems, 512 threads)
    for (int k = 2; k <= NN; k <<= 1) {
        for (int j = k >> 1; j > 0; j >>= 1) {
            int ixj = tid ^ j;
            if (ixj > tid) {
                float a = t_sh[tid];
                float b = t_sh[ixj];
                bool desc = ((tid & k) == 0);
                if (desc ? (a < b) : (a > b)) { t_sh[tid] = b; t_sh[ixj] = a; }
            }
            __syncthreads();
        }
    }

    // lane-resident operands: lane handles indices {lane + 32*q}
    float s_r[16], t_r[16];
#pragma unroll
    for (int q = 0; q < 16; q++) {
        s_r[q] = s_sh[lane + 32 * q];
        t_r[q] = t_sh[lane + 32 * q];
    }

    const float nk2 = -1442.6950408889634f;   // -log2(e)/EPSILON
    const uint32_t Ub = smem_u32(U_sh);
    const uint32_t Vb = smem_u32(V_sh);
    const int base = rank * RPC + warp * 4;   // 4 rows/cols per warp

    for (int it = 0; it < NITERS; it++) {
        // ---- half-step 1: columns (reduce over i) ----
        float Ur[16];
#pragma unroll
        for (int q = 0; q < 16; q++) Ur[q] = U_sh[lane + 32 * q];
#pragma unroll 1
        for (int c = 0; c < 4; c++) {
            const int j = base + c;
            const float tj = t_sh[j];
            float x[16];
            float m = -3.402823466e38f;
#pragma unroll
            for (int q = 0; q < 16; q++) {
                float d = s_r[q] - tj;
                x[q] = fmaf(d * nk2, d, Ur[q]);
                m = fmaxf(m, x[q]);
            }
#pragma unroll
            for (int o = 16; o > 0; o >>= 1)
                m = fmaxf(m, __shfl_xor_sync(0xffffffffu, m, o));
            float sum = 0.0f;
#pragma unroll
            for (int q = 0; q < 16; q++) sum += ex2f_(x[q] - m);
#pragma unroll
            for (int o = 16; o > 0; o >>= 1)
                sum += __shfl_xor_sync(0xffffffffu, sum, o);
            const float vj = -(m + lg2f_(sum));       // all lanes hold it
            if (lane < CL) st_cluster_f32(Vb + (uint32_t)j * 4u, (uint32_t)lane, vj);
        }
        cluster_sync_();

        // ---- half-step 2: rows (reduce over j) ----
        float Vr[16];
#pragma unroll
        for (int q = 0; q < 16; q++) Vr[q] = V_sh[lane + 32 * q];
#pragma unroll 1
        for (int c = 0; c < 4; c++) {
            const int i = base + c;
            const float si = s_sh[i];
            float x[16];
            float m = -3.402823466e38f;
#pragma unroll
            for (int q = 0; q < 16; q++) {
                float d = si - t_r[q];
                x[q] = fmaf(d * nk2, d, Vr[q]);
                m = fmaxf(m, x[q]);
            }
#pragma unroll
            for (int o = 16; o > 0; o >>= 1)
                m = fmaxf(m, __shfl_xor_sync(0xffffffffu, m, o));
            float sum = 0.0f;
#pragma unroll
            for (int q = 0; q < 16; q++) sum += ex2f_(x[q] - m);
#pragma unroll
            for (int o = 16; o > 0; o >>= 1)
                sum += __shfl_xor_sync(0xffffffffu, sum, o);
            const float ui = -(m + lg2f_(sum));
            if (lane < CL) st_cluster_f32(Ub + (uint32_t)i * 4u, (uint32_t)lane, ui);
        }
        cluster_sync_();
    }

    // ---- output: out[i] = sum_{j<K} 2^(L_ij + U_i + V_j) ----
#pragma unroll 1
    for (int c = 0; c < 4; c++) {
        const int i = base + c;
        const float si = s_sh[i];
        const float ui = U_sh[i];
        float acc = 0.0f;
        for (int jj = lane; jj < KTOP; jj += 32) {
            float d = si - t_sh[jj];
            acc += ex2f_(fmaf(d * nk2, d, ui + V_sh[jj]));
        }
#pragma unroll
        for (int o = 16; o > 0; o >>= 1)
            acc += __shfl_xor_sync(0xffffffffu, acc, o);
        if (lane == 0) out[batch * NN + i] = acc;
    }
}

extern "C" void kernel_launch(void* const* d_in, const int* in_sizes, int n_in,
                              void* d_out, int out_size) {
    const float* scores = (const float*)d_in[0];
    float* outp = (float*)d_out;
    sinkhorn_topk_kernel<<<NB * CL, NTHREADS>>>(scores, outp);
}

// round 4
// speedup vs baseline: 1.1266x; 1.1172x over previous
#include <cuda_runtime.h>
#include <cstdint>

#define NN       512
#define NB       16
#define KTOP     50
#define NITERS   100
#define CL       8      // CTAs per cluster (one cluster per batch)
#define RPC      64     // rows owned per CTA
#define NTHREADS 512

__device__ __forceinline__ uint32_t smem_u32(const void* p) {
    return (uint32_t)__cvta_generic_to_shared(p);
}
__device__ __forceinline__ float ex2f_(float x) {
    float r; asm("ex2.approx.ftz.f32 %0, %1;" : "=f"(r) : "f"(x)); return r;
}
__device__ __forceinline__ float lg2f_(float x) {
    float r; asm("lg2.approx.f32 %0, %1;" : "=f"(r) : "f"(x)); return r;
}
__device__ __forceinline__ void cluster_sync_() {
    asm volatile("barrier.cluster.arrive.aligned;" ::: "memory");
    asm volatile("barrier.cluster.wait.aligned;" ::: "memory");
}
__device__ __forceinline__ uint32_t ctarank_() {
    uint32_t r; asm("mov.u32 %0, %%cluster_ctarank;" : "=r"(r)); return r;
}
// Store val to the same smem offset in cluster CTA `rank` (includes self).
__device__ __forceinline__ void st_cluster_f32(uint32_t laddr, uint32_t rank, float v) {
    asm volatile(
        "{\n\t.reg .b32 ra;\n\t"
        "mapa.shared::cluster.u32 ra, %0, %1;\n\t"
        "st.shared::cluster.f32 [ra], %2;\n\t}"
        :: "r"(laddr), "r"(rank), "f"(v) : "memory");
}

// One half-step: for the warp's 4 owned rows a, compute
//   dst[a] = -lse2_b( M[a,b] + W[b] )
// M rows live in SMEM (precomputed, iteration-invariant), W in SMEM.
// Rows processed in interleaved pairs for ILP.
__device__ __forceinline__ void half_step(
    const float* __restrict__ Msh, const float* __restrict__ Wsh,
    uint32_t dstb, int rowbase, int gbase, int lane)
{
    // load W once per half-step (shared across the warp's 4 rows)
    float w[16];
    {
        const float4* W4 = (const float4*)Wsh;
#pragma unroll
        for (int q = 0; q < 4; q++) {
            float4 t = W4[lane + 32 * q];
            w[4*q+0] = t.x; w[4*q+1] = t.y; w[4*q+2] = t.z; w[4*q+3] = t.w;
        }
    }

#pragma unroll
    for (int pair = 0; pair < 2; pair++) {
        const int r0 = rowbase + 2 * pair;
        const float4* M0 = (const float4*)(Msh + (size_t)r0 * NN);
        const float4* M1 = (const float4*)(Msh + (size_t)(r0 + 1) * NN);

        float x0[16], x1[16];
        float mx0 = -3.402823466e38f, mx1 = -3.402823466e38f;
#pragma unroll
        for (int q = 0; q < 4; q++) {
            float4 a = M0[lane + 32 * q];
            float4 b = M1[lane + 32 * q];
            x0[4*q+0] = a.x + w[4*q+0]; x1[4*q+0] = b.x + w[4*q+0];
            x0[4*q+1] = a.y + w[4*q+1]; x1[4*q+1] = b.y + w[4*q+1];
            x0[4*q+2] = a.z + w[4*q+2]; x1[4*q+2] = b.z + w[4*q+2];
            x0[4*q+3] = a.w + w[4*q+3]; x1[4*q+3] = b.w + w[4*q+3];
            mx0 = fmaxf(mx0, fmaxf(fmaxf(x0[4*q+0], x0[4*q+1]), fmaxf(x0[4*q+2], x0[4*q+3])));
            mx1 = fmaxf(mx1, fmaxf(fmaxf(x1[4*q+0], x1[4*q+1]), fmaxf(x1[4*q+2], x1[4*q+3])));
        }
#pragma unroll
        for (int o = 16; o > 0; o >>= 1) {
            mx0 = fmaxf(mx0, __shfl_xor_sync(0xffffffffu, mx0, o));
            mx1 = fmaxf(mx1, __shfl_xor_sync(0xffffffffu, mx1, o));
        }

        float s0a = 0.f, s0b = 0.f, s0c = 0.f, s0d = 0.f;
        float s1a = 0.f, s1b = 0.f, s1c = 0.f, s1d = 0.f;
#pragma unroll
        for (int q = 0; q < 4; q++) {
            s0a += ex2f_(x0[4*q+0] - mx0);
            s0b += ex2f_(x0[4*q+1] - mx0);
            s0c += ex2f_(x0[4*q+2] - mx0);
            s0d += ex2f_(x0[4*q+3] - mx0);
            s1a += ex2f_(x1[4*q+0] - mx1);
            s1b += ex2f_(x1[4*q+1] - mx1);
            s1c += ex2f_(x1[4*q+2] - mx1);
            s1d += ex2f_(x1[4*q+3] - mx1);
        }
        float sum0 = (s0a + s0b) + (s0c + s0d);
        float sum1 = (s1a + s1b) + (s1c + s1d);
#pragma unroll
        for (int o = 16; o > 0; o >>= 1) {
            sum0 += __shfl_xor_sync(0xffffffffu, sum0, o);
            sum1 += __shfl_xor_sync(0xffffffffu, sum1, o);
        }
        const float v0 = -(mx0 + lg2f_(sum0));
        const float v1 = -(mx1 + lg2f_(sum1));
        if (lane < CL) {
            st_cluster_f32(dstb + (uint32_t)(gbase + 2 * pair) * 4u, (uint32_t)lane, v0);
            st_cluster_f32(dstb + (uint32_t)(gbase + 2 * pair + 1) * 4u, (uint32_t)lane, v1);
        }
    }
}

// log_P = L + U[i] + V[j],  L[i,j] = nk2*(s_i - t_j)^2 (log2 domain), t = sort_desc(s).
// With t_j = s[p[j]]:  L[i,j] = M[i, p[j]] where M[a,b] = nk2*(s_a - s_b)^2 is SYMMETRIC.
// Writing Vp[p[j]] = V_j, both half-steps reduce over rows of M:
//   step 1:  Vp[a] = -lse2_b( M[a,b] + U[b]  )
//   step 2:  U[a]  = -lse2_b( M[a,b] + Vp[b] )
__global__ void __launch_bounds__(NTHREADS, 1) __cluster_dims__(CL, 1, 1)
sinkhorn_topk_kernel(const float* __restrict__ scores, float* __restrict__ out)
{
    extern __shared__ float Msh[];                 // [RPC][NN] = 128 KB
    __shared__ __align__(16) float s_sh[NN];       // scores (original order)
    __shared__ __align__(16) float U_sh[NN];       // row potentials
    __shared__ __align__(16) float Vp_sh[NN];      // col potentials, original-index order
    __shared__ __align__(16) float t_sh[NN];       // sorted descending (output only)
    __shared__ int p_sh[NN];                       // sorted pos -> original index

    const int tid   = threadIdx.x;
    const int lane  = tid & 31;
    const int warp  = tid >> 5;
    const int rank  = (int)ctarank_();
    const int batch = blockIdx.x / CL;
    const float nk2 = -1442.6950408889634f;        // -log2(e)/EPSILON

    float sv = scores[batch * NN + tid];
    s_sh[tid] = sv;
    t_sh[tid] = sv;
    p_sh[tid] = tid;
    U_sh[tid] = 0.0f;
    Vp_sh[tid] = 0.0f;
    __syncthreads();

    // Bitonic sort (value, index) descending — output phase only
    for (int k = 2; k <= NN; k <<= 1) {
        for (int j = k >> 1; j > 0; j >>= 1) {
            int ixj = tid ^ j;
            if (ixj > tid) {
                float a = t_sh[tid], b = t_sh[ixj];
                bool desc = ((tid & k) == 0);
                if (desc ? (a < b) : (a > b)) {
                    t_sh[tid] = b; t_sh[ixj] = a;
                    int pa = p_sh[tid]; p_sh[tid] = p_sh[ixj]; p_sh[ixj] = pa;
                }
            }
            __syncthreads();
        }
    }

    // Build this CTA's 64 rows of M (iteration-invariant)
    {
        const int abase = rank * RPC;
        const float se = s_sh[tid];
#pragma unroll 4
        for (int c = 0; c < RPC; c++) {
            float d = s_sh[abase + c] - se;
            Msh[c * NN + tid] = (d * nk2) * d;
        }
    }
    __syncthreads();
    cluster_sync_();   // everyone's U/Vp init + M done before any peer stores arrive

    const uint32_t Ub = smem_u32(U_sh);
    const uint32_t Vb = smem_u32(Vp_sh);
    const int rowbase = warp * 4;              // within-CTA row
    const int gbase   = rank * RPC + rowbase;  // global row index

    for (int it = 0; it < NITERS; it++) {
        half_step(Msh, U_sh,  Vb, rowbase, gbase, lane);   // -> Vp
        cluster_sync_();
        half_step(Msh, Vp_sh, Ub, rowbase, gbase, lane);   // -> U
        cluster_sync_();
    }

    // out[i] = sum_{j<K} 2^( nk2*(s_i - t_j)^2 + U_i + Vp[p[j]] )
#pragma unroll 1
    for (int c = 0; c < 4; c++) {
        const int i = gbase + c;
        const float si = s_sh[i];
        const float ui = U_sh[i];
        float acc = 0.0f;
        for (int jj = lane; jj < KTOP; jj += 32) {
            float d = si - t_sh[jj];
            acc += ex2f_(fmaf(d * nk2, d, ui + Vp_sh[p_sh[jj]]));
        }
#pragma unroll
        for (int o = 16; o > 0; o >>= 1)
            acc += __shfl_xor_sync(0xffffffffu, acc, o);
        if (lane == 0) out[batch * NN + i] = acc;
    }
}

extern "C" void kernel_launch(void* const* d_in, const int* in_sizes, int n_in,
                              void* d_out, int out_size) {
    const float* scores = (const float*)d_in[0];
    float* outp = (float*)d_out;
    cudaFuncSetAttribute(sinkhorn_topk_kernel,
                         cudaFuncAttributeMaxDynamicSharedMemorySize,
                         RPC * NN * (int)sizeof(float));
    sinkhorn_topk_kernel<<<NB * CL, NTHREADS, RPC * NN * sizeof(float)>>>(scores, outp);
}

// round 6
// speedup vs baseline: 1.1268x; 1.0002x over previous
#include <cuda_runtime.h>
#include <cstdint>

#define NN       512
#define NB       16
#define KTOP     50
#define NITERS   100
#define CL       8      // CTAs per cluster (one cluster per batch)
#define RPC      64     // sorted rows owned per CTA
#define NTHREADS 512
#define CUT      30.0f  // block-skip threshold in log2 units

__device__ __forceinline__ uint32_t smem_u32(const void* p) {
    return (uint32_t)__cvta_generic_to_shared(p);
}
__device__ __forceinline__ float ex2f_(float x) {
    float r; asm("ex2.approx.ftz.f32 %0, %1;" : "=f"(r) : "f"(x)); return r;
}
__device__ __forceinline__ float lg2f_(float x) {
    float r; asm("lg2.approx.f32 %0, %1;" : "=f"(r) : "f"(x)); return r;
}
// warp-max of a float via order-preserving u32 mapping + redux.sync.max.u32
__device__ __forceinline__ float warp_max_f32(float x) {
    int32_t b = __float_as_int(x);
    uint32_t u = (uint32_t)b ^ (uint32_t)((b >> 31) | 0x80000000);
    uint32_t r;
    asm("redux.sync.max.u32 %0, %1, 0xffffffff;" : "=r"(r) : "r"(u));
    uint32_t bb = r ^ ((~(uint32_t)((int32_t)r >> 31)) | 0x80000000u);
    return __int_as_float((int32_t)bb);
}
__device__ __forceinline__ void cluster_sync_() {
    asm volatile("barrier.cluster.arrive.aligned;" ::: "memory");
    asm volatile("barrier.cluster.wait.aligned;" ::: "memory");
}
__device__ __forceinline__ uint32_t ctarank_() {
    uint32_t r; asm("mov.u32 %0, %%cluster_ctarank;" : "=r"(r)); return r;
}
__device__ __forceinline__ void st_cluster_f32(uint32_t laddr, uint32_t rank, float v) {
    asm volatile(
        "{\n\t.reg .b32 ra;\n\t"
        "mapa.shared::cluster.u32 ra, %0, %1;\n\t"
        "st.shared::cluster.f32 [ra], %2;\n\t}"
        :: "r"(laddr), "r"(rank), "f"(v) : "memory");
}

// One half-step in sorted space: for the warp's 4 owned rows a (2 interleaved pairs),
//   dst[a] = -lse2_b( M[a,b] + W[b] )
// Pass 1: exact row max over all 512 cols (FADD/FMNMX, W register-resident).
// Vote: 128-col blocks with any x > max-CUT. Pass 2: exp-sum over active blocks only.
__device__ __forceinline__ void half_step(
    const float* __restrict__ Msh, const float* __restrict__ Wsh,
    uint32_t dstb, int rowbase, int gbase, int lane)
{
    const float4* W4 = (const float4*)Wsh;
    float w[16];
#pragma unroll
    for (int q = 0; q < 4; q++) {
        float4 t = W4[32 * q + lane];
        w[4*q+0] = t.x; w[4*q+1] = t.y; w[4*q+2] = t.z; w[4*q+3] = t.w;
    }

#pragma unroll
    for (int pair = 0; pair < 2; pair++) {
        const int r0 = rowbase + 2 * pair;
        const float4* M0 = (const float4*)(Msh + (size_t)r0 * NN);
        const float4* M1 = (const float4*)(Msh + (size_t)(r0 + 1) * NN);

        // pass 1: per-block lane maxes of x = M + w
        float mq0[4], mq1[4];
#pragma unroll
        for (int q = 0; q < 4; q++) {
            float4 a = M0[32 * q + lane];
            float4 b = M1[32 * q + lane];
            float a0 = a.x + w[4*q+0], a1 = a.y + w[4*q+1];
            float a2 = a.z + w[4*q+2], a3 = a.w + w[4*q+3];
            float b0 = b.x + w[4*q+0], b1 = b.y + w[4*q+1];
            float b2 = b.z + w[4*q+2], b3 = b.w + w[4*q+3];
            mq0[q] = fmaxf(fmaxf(a0, a1), fmaxf(a2, a3));
            mq1[q] = fmaxf(fmaxf(b0, b1), fmaxf(b2, b3));
        }
        const float m0 = warp_max_f32(fmaxf(fmaxf(mq0[0], mq0[1]), fmaxf(mq0[2], mq0[3])));
        const float m1 = warp_max_f32(fmaxf(fmaxf(mq1[0], mq1[1]), fmaxf(mq1[2], mq1[3])));
        const float c0 = m0 - CUT, c1 = m1 - CUT;

        // active-block mask (warp-uniform), rows of a pair share the range
        unsigned mask = 0;
#pragma unroll
        for (int q = 0; q < 4; q++)
            if (__any_sync(0xffffffffu, (mq0[q] > c0) || (mq1[q] > c1)))
                mask |= 1u << q;
        const int lo = __ffs(mask) - 1;
        const int hi = 31 - __clz(mask);

        // pass 2: exp-sum over active blocks (reload M, W from SMEM: runtime q)
        float s0a = 0.f, s0b = 0.f, s0c = 0.f, s0d = 0.f;
        float s1a = 0.f, s1b = 0.f, s1c = 0.f, s1d = 0.f;
        for (int q = lo; q <= hi; q++) {
            float4 a  = M0[32 * q + lane];
            float4 b  = M1[32 * q + lane];
            float4 ww = W4[32 * q + lane];
            s0a += ex2f_((a.x + ww.x) - m0);
            s0b += ex2f_((a.y + ww.y) - m0);
            s0c += ex2f_((a.z + ww.z) - m0);
            s0d += ex2f_((a.w + ww.w) - m0);
            s1a += ex2f_((b.x + ww.x) - m1);
            s1b += ex2f_((b.y + ww.y) - m1);
            s1c += ex2f_((b.z + ww.z) - m1);
            s1d += ex2f_((b.w + ww.w) - m1);
        }
        float sum0 = (s0a + s0b) + (s0c + s0d);
        float sum1 = (s1a + s1b) + (s1c + s1d);
#pragma unroll
        for (int o = 16; o > 0; o >>= 1) {
            sum0 += __shfl_xor_sync(0xffffffffu, sum0, o);
            sum1 += __shfl_xor_sync(0xffffffffu, sum1, o);
        }
        const float v0 = -(m0 + lg2f_(sum0));
        const float v1 = -(m1 + lg2f_(sum1));
        if (lane < CL) {
            st_cluster_f32(dstb + (uint32_t)(gbase + 2 * pair) * 4u, (uint32_t)lane, v0);
            st_cluster_f32(dstb + (uint32_t)(gbase + 2 * pair + 1) * 4u, (uint32_t)lane, v1);
        }
    }
}

// Everything in sorted coordinate space: t = sort_desc(s), p: sorted pos -> original idx.
// M[a,b] = nk2*(t_a - t_b)^2 (symmetric, band-dominant around the diagonal).
//   step 1:  V[a] = -lse2_b( M[a,b] + U[b] )   (V indexed by sorted col position)
//   step 2:  U[a] = -lse2_b( M[a,b] + V[b] )   (U indexed by sorted row position)
// out[p[a]] = sum_{j<K} 2^( M[a,j] + U[a] + V[j] )
__global__ void __launch_bounds__(NTHREADS, 1) __cluster_dims__(CL, 1, 1)
sinkhorn_topk_kernel(const float* __restrict__ scores, float* __restrict__ out)
{
    extern __shared__ float Msh[];                 // [RPC][NN] = 128 KB
    __shared__ __align__(16) float t_sh[NN];       // sorted descending
    __shared__ __align__(16) float U_sh[NN];       // row potentials (sorted space)
    __shared__ __align__(16) float V_sh[NN];       // col potentials (sorted space)
    __shared__ int p_sh[NN];                       // sorted pos -> original index

    const int tid   = threadIdx.x;
    const int lane  = tid & 31;
    const int warp  = tid >> 5;
    const int rank  = (int)ctarank_();
    const int batch = blockIdx.x / CL;
    const float nk2 = -1442.6950408889634f;        // -log2(e)/EPSILON

    t_sh[tid] = scores[batch * NN + tid];
    p_sh[tid] = tid;
    U_sh[tid] = 0.0f;
    V_sh[tid] = 0.0f;
    __syncthreads();

    // Bitonic sort (value, index) descending
    for (int k = 2; k <= NN; k <<= 1) {
        for (int j = k >> 1; j > 0; j >>= 1) {
            int ixj = tid ^ j;
            if (ixj > tid) {
                float a = t_sh[tid], b = t_sh[ixj];
                bool desc = ((tid & k) == 0);
                if (desc ? (a < b) : (a > b)) {
                    t_sh[tid] = b; t_sh[ixj] = a;
                    int pa = p_sh[tid]; p_sh[tid] = p_sh[ixj]; p_sh[ixj] = pa;
                }
            }
            __syncthreads();
        }
    }

    // Build this CTA's 64 sorted-space rows of M (iteration-invariant)
    {
        const int abase = rank * RPC;
        const float te = t_sh[tid];
#pragma unroll 4
        for (int c = 0; c < RPC; c++) {
            float d = t_sh[abase + c] - te;
            Msh[c * NN + tid] = (d * nk2) * d;
        }
    }
    __syncthreads();
    cluster_sync_();   // all CTAs' U/V init + M done before any peer stores arrive

    const uint32_t Ub = smem_u32(U_sh);
    const uint32_t Vb = smem_u32(V_sh);
    const int rowbase = warp * 4;              // within-CTA row
    const int gbase   = rank * RPC + rowbase;  // global sorted row index

    for (int it = 0; it < NITERS; it++) {
        half_step(Msh, U_sh, Vb, rowbase, gbase, lane);   // -> V
        cluster_sync_();
        half_step(Msh, V_sh, Ub, rowbase, gbase, lane);   // -> U
        cluster_sync_();
    }

    // out[p[a]] = sum_{j<K} 2^( nk2*(t_a - t_j)^2 + U[a] + V[j] )
#pragma unroll 1
    for (int c = 0; c < 4; c++) {
        const int a = gbase + c;
        const float ta = t_sh[a];
        const float ua = U_sh[a];
        float acc = 0.0f;
        for (int jj = lane; jj < KTOP; jj += 32) {
            float d = ta - t_sh[jj];
            acc += ex2f_(fmaf(d * nk2, d, ua + V_sh[jj]));
        }
#pragma unroll
        for (int o = 16; o > 0; o >>= 1)
            acc += __shfl_xor_sync(0xffffffffu, acc, o);
        if (lane == 0) out[batch * NN + p_sh[a]] = acc;
    }
}

extern "C" void kernel_launch(void* const* d_in, const int* in_sizes, int n_in,
                              void* d_out, int out_size) {
    const float* scores = (const float*)d_in[0];
    float* outp = (float*)d_out;
    cudaFuncSetAttribute(sinkhorn_topk_kernel,
                         cudaFuncAttributeMaxDynamicSharedMemorySize,
                         RPC * NN * (int)sizeof(float));
    sinkhorn_topk_kernel<<<NB * CL, NTHREADS, RPC * NN * sizeof(float)>>>(scores, outp);
}

// round 7
// speedup vs baseline: 1.2446x; 1.1045x over previous
#include <cuda_runtime.h>
#include <cstdint>

#define NN       512
#define NB       16
#define KTOP     50
#define NITERS   100
#define CL       8      // CTAs per cluster (one cluster per batch)
#define RPC      64     // sorted rows owned per CTA
#define NTHREADS 1024   // 32 warps, 2 rows per warp
#define CUT      30.0f  // block-skip threshold in log2 units

__device__ __forceinline__ uint32_t smem_u32(const void* p) {
    return (uint32_t)__cvta_generic_to_shared(p);
}
__device__ __forceinline__ float ex2f_(float x) {
    float r; asm("ex2.approx.ftz.f32 %0, %1;" : "=f"(r) : "f"(x)); return r;
}
__device__ __forceinline__ float lg2f_(float x) {
    float r; asm("lg2.approx.f32 %0, %1;" : "=f"(r) : "f"(x)); return r;
}
// warp-max of a float via order-preserving u32 mapping + redux.sync.max.u32
__device__ __forceinline__ float warp_max_f32(float x) {
    int32_t b = __float_as_int(x);
    uint32_t u = (uint32_t)b ^ (uint32_t)((b >> 31) | 0x80000000);
    uint32_t r;
    asm("redux.sync.max.u32 %0, %1, 0xffffffff;" : "=r"(r) : "r"(u));
    uint32_t bb = r ^ ((~(uint32_t)((int32_t)r >> 31)) | 0x80000000u);
    return __int_as_float((int32_t)bb);
}
__device__ __forceinline__ void cluster_sync_() {
    asm volatile("barrier.cluster.arrive.aligned;" ::: "memory");
    asm volatile("barrier.cluster.wait.aligned;" ::: "memory");
}
__device__ __forceinline__ uint32_t ctarank_() {
    uint32_t r; asm("mov.u32 %0, %%cluster_ctarank;" : "=r"(r)); return r;
}
__device__ __forceinline__ void st_cluster_f32(uint32_t laddr, uint32_t rank, float v) {
    asm volatile(
        "{\n\t.reg .b32 ra;\n\t"
        "mapa.shared::cluster.u32 ra, %0, %1;\n\t"
        "st.shared::cluster.f32 [ra], %2;\n\t}"
        :: "r"(laddr), "r"(rank), "f"(v) : "memory");
}

// One half-step in sorted space: each warp owns 2 rows (one interleaved pair):
//   dst[a] = -lse2_b( M[a,b] + W[b] )
// Pass 1: exact row max over all 512 cols (W register-resident).
// Pass 2: exp-sum over 128-col blocks surviving the CUT, predicated unrolled
// (static register indexing of w[], no W reload).
__device__ __forceinline__ void half_step(
    const float* __restrict__ Msh, const float* __restrict__ Wsh,
    uint32_t dstb, int rowbase, int gbase, int lane)
{
    const float4* W4 = (const float4*)Wsh;
    float w[16];
#pragma unroll
    for (int q = 0; q < 4; q++) {
        float4 t = W4[32 * q + lane];
        w[4*q+0] = t.x; w[4*q+1] = t.y; w[4*q+2] = t.z; w[4*q+3] = t.w;
    }

    const float4* M0 = (const float4*)(Msh + (size_t)rowbase * NN);
    const float4* M1 = (const float4*)(Msh + (size_t)(rowbase + 1) * NN);

    // pass 1: per-block lane maxes of x = M + w
    float mq0[4], mq1[4];
#pragma unroll
    for (int q = 0; q < 4; q++) {
        float4 a = M0[32 * q + lane];
        float4 b = M1[32 * q + lane];
        float a0 = a.x + w[4*q+0], a1 = a.y + w[4*q+1];
        float a2 = a.z + w[4*q+2], a3 = a.w + w[4*q+3];
        float b0 = b.x + w[4*q+0], b1 = b.y + w[4*q+1];
        float b2 = b.z + w[4*q+2], b3 = b.w + w[4*q+3];
        mq0[q] = fmaxf(fmaxf(a0, a1), fmaxf(a2, a3));
        mq1[q] = fmaxf(fmaxf(b0, b1), fmaxf(b2, b3));
    }
    const float m0 = warp_max_f32(fmaxf(fmaxf(mq0[0], mq0[1]), fmaxf(mq0[2], mq0[3])));
    const float m1 = warp_max_f32(fmaxf(fmaxf(mq1[0], mq1[1]), fmaxf(mq1[2], mq1[3])));
    const float c0 = m0 - CUT, c1 = m1 - CUT;

    // active-block mask (warp-uniform); both rows of the pair share it
    unsigned mask = 0;
#pragma unroll
    for (int q = 0; q < 4; q++)
        if (__any_sync(0xffffffffu, (mq0[q] > c0) || (mq1[q] > c1)))
            mask |= 1u << q;

    // pass 2: exp-sum over active blocks (predicated unroll, w in registers)
    float s0a = 0.f, s0b = 0.f, s0c = 0.f, s0d = 0.f;
    float s1a = 0.f, s1b = 0.f, s1c = 0.f, s1d = 0.f;
#pragma unroll
    for (int q = 0; q < 4; q++) {
        if (mask & (1u << q)) {
            float4 a = M0[32 * q + lane];
            float4 b = M1[32 * q + lane];
            s0a += ex2f_((a.x + w[4*q+0]) - m0);
            s0b += ex2f_((a.y + w[4*q+1]) - m0);
            s0c += ex2f_((a.z + w[4*q+2]) - m0);
            s0d += ex2f_((a.w + w[4*q+3]) - m0);
            s1a += ex2f_((b.x + w[4*q+0]) - m1);
            s1b += ex2f_((b.y + w[4*q+1]) - m1);
            s1c += ex2f_((b.z + w[4*q+2]) - m1);
            s1d += ex2f_((b.w + w[4*q+3]) - m1);
        }
    }
    float sum0 = (s0a + s0b) + (s0c + s0d);
    float sum1 = (s1a + s1b) + (s1c + s1d);
#pragma unroll
    for (int o = 16; o > 0; o >>= 1) {
        sum0 += __shfl_xor_sync(0xffffffffu, sum0, o);
        sum1 += __shfl_xor_sync(0xffffffffu, sum1, o);
    }
    const float v0 = -(m0 + lg2f_(sum0));
    const float v1 = -(m1 + lg2f_(sum1));
    if (lane < CL) {
        st_cluster_f32(dstb + (uint32_t)(gbase)     * 4u, (uint32_t)lane, v0);
        st_cluster_f32(dstb + (uint32_t)(gbase + 1) * 4u, (uint32_t)lane, v1);
    }
}

// Sorted coordinate space: t = sort_desc(s), p: sorted pos -> original idx.
// M[a,b] = nk2*(t_a - t_b)^2 (symmetric, band-dominant).
//   step 1:  V[a] = -lse2_b( M[a,b] + U[b] )
//   step 2:  U[a] = -lse2_b( M[a,b] + V[b] )
// out[p[a]] = sum_{j<K} 2^( M[a,j] + U[a] + V[j] )
__global__ void __launch_bounds__(NTHREADS, 1) __cluster_dims__(CL, 1, 1)
sinkhorn_topk_kernel(const float* __restrict__ scores, float* __restrict__ out)
{
    extern __shared__ float Msh[];                 // [RPC][NN] = 128 KB
    __shared__ __align__(16) float t_sh[NN];       // sorted descending
    __shared__ __align__(16) float U_sh[NN];       // row potentials (sorted space)
    __shared__ __align__(16) float V_sh[NN];       // col potentials (sorted space)
    __shared__ int p_sh[NN];                       // sorted pos -> original index

    const int tid   = threadIdx.x;
    const int lane  = tid & 31;
    const int warp  = tid >> 5;
    const int rank  = (int)ctarank_();
    const int batch = blockIdx.x / CL;
    const float nk2 = -1442.6950408889634f;        // -log2(e)/EPSILON

    if (tid < NN) {
        t_sh[tid] = scores[batch * NN + tid];
        p_sh[tid] = tid;
        U_sh[tid] = 0.0f;
        V_sh[tid] = 0.0f;
    }
    __syncthreads();

    // Bitonic sort (value, index) descending — threads 0..511 active
    for (int k = 2; k <= NN; k <<= 1) {
        for (int j = k >> 1; j > 0; j >>= 1) {
            if (tid < NN) {
                int ixj = tid ^ j;
                if (ixj > tid) {
                    float a = t_sh[tid], b = t_sh[ixj];
                    bool desc = ((tid & k) == 0);
                    if (desc ? (a < b) : (a > b)) {
                        t_sh[tid] = b; t_sh[ixj] = a;
                        int pa = p_sh[tid]; p_sh[tid] = p_sh[ixj]; p_sh[ixj] = pa;
                    }
                }
            }
            __syncthreads();
        }
    }

    // Build this CTA's 64 sorted-space rows of M (iteration-invariant)
    {
        const int abase = rank * RPC;
        const int col = tid & (NN - 1);          // 0..511
        const int c0  = (tid >> 9) * (RPC / 2);  // rows 0..31 / 32..63
        const float te = t_sh[col];
#pragma unroll 4
        for (int c = c0; c < c0 + RPC / 2; c++) {
            float d = t_sh[abase + c] - te;
            Msh[c * NN + col] = (d * nk2) * d;
        }
    }
    __syncthreads();
    cluster_sync_();   // all CTAs' U/V init + M done before any peer stores arrive

    const uint32_t Ub = smem_u32(U_sh);
    const uint32_t Vb = smem_u32(V_sh);
    const int rowbase = warp * 2;              // 2 rows per warp
    const int gbase   = rank * RPC + rowbase;  // global sorted row index

    for (int it = 0; it < NITERS; it++) {
        half_step(Msh, U_sh, Vb, rowbase, gbase, lane);   // -> V
        cluster_sync_();
        half_step(Msh, V_sh, Ub, rowbase, gbase, lane);   // -> U
        cluster_sync_();
    }

    // out[p[a]] = sum_{j<K} 2^( nk2*(t_a - t_j)^2 + U[a] + V[j] )
#pragma unroll
    for (int c = 0; c < 2; c++) {
        const int a = gbase + c;
        const float ta = t_sh[a];
        const float ua = U_sh[a];
        float acc = 0.0f;
        for (int jj = lane; jj < KTOP; jj += 32) {
            float d = ta - t_sh[jj];
            acc += ex2f_(fmaf(d * nk2, d, ua + V_sh[jj]));
        }
#pragma unroll
        for (int o = 16; o > 0; o >>= 1)
            acc += __shfl_xor_sync(0xffffffffu, acc, o);
        if (lane == 0) out[batch * NN + p_sh[a]] = acc;
    }
}

extern "C" void kernel_launch(void* const* d_in, const int* in_sizes, int n_in,
                              void* d_out, int out_size) {
    const float* scores = (const float*)d_in[0];
    float* outp = (float*)d_out;
    cudaFuncSetAttribute(sinkhorn_topk_kernel,
                         cudaFuncAttributeMaxDynamicSharedMemorySize,
                         RPC * NN * (int)sizeof(float));
    sinkhorn_topk_kernel<<<NB * CL, NTHREADS, RPC * NN * sizeof(float)>>>(scores, outp);
}